// round 4
// baseline (speedup 1.0000x reference)
#include <cuda_runtime.h>
#include <math.h>

typedef unsigned long long u64;

// ---- packed f32x2 helpers (sm_103a FFMA2 path; ptxas never emits from C) ----
__device__ __forceinline__ u64 pk2(float lo, float hi) {
    u64 r; asm("mov.b64 %0,{%1,%2};" : "=l"(r) : "f"(lo), "f"(hi)); return r;
}
__device__ __forceinline__ void upk2(float& lo, float& hi, u64 v) {
    asm("mov.b64 {%0,%1},%2;" : "=f"(lo), "=f"(hi) : "l"(v));
}
__device__ __forceinline__ u64 fma2(u64 a, u64 b, u64 c) {
    u64 d; asm("fma.rn.f32x2 %0,%1,%2,%3;" : "=l"(d) : "l"(a), "l"(b), "l"(c)); return d;
}
__device__ __forceinline__ u64 mul2(u64 a, u64 b) {
    u64 d; asm("mul.rn.f32x2 %0,%1,%2;" : "=l"(d) : "l"(a), "l"(b)); return d;
}

// ---------------------------------------------------------------------------
// Gate templates (compile-time masks). Wire w <-> bit (3-w) of amp index.
// ---------------------------------------------------------------------------
template<int M>
__device__ __forceinline__ void ry_gate(float sr[16], float si[16], float c, float s) {
#pragma unroll
    for (int i = 0; i < 16; i++) {
        if (!(i & M)) {
            const int j = i | M;
            float a0r = sr[i], a0i = si[i], a1r = sr[j], a1i = si[j];
            sr[i] = c * a0r - s * a1r;
            si[i] = c * a0i - s * a1i;
            sr[j] = s * a0r + c * a1r;
            si[j] = s * a0i + c * a1i;
        }
    }
}

template<int M>
__device__ __forceinline__ void rz_gate(float sr[16], float si[16], float c, float s) {
#pragma unroll
    for (int i = 0; i < 16; i++) {
        float sg = (i & M) ? s : -s;
        float rr = sr[i], ii = si[i];
        sr[i] = c * rr - sg * ii;
        si[i] = c * ii + sg * rr;
    }
}

template<int CM, int TM>
__device__ __forceinline__ void cx_gate(float sr[16], float si[16]) {
#pragma unroll
    for (int i = 0; i < 16; i++) {
        if ((i & CM) && !(i & TM)) {
            const int j = i | TM;
            float t;
            t = sr[i]; sr[i] = sr[j]; sr[j] = t;
            t = si[i]; si[i] = si[j]; si[j] = t;
        }
    }
}

// Coefficient tensor, layout [i(a12)][w][10] (j pairs + zero pad): 9*4*10 = 360.
__device__ float g_A[9 * 40];

// ---------------------------------------------------------------------------
// Precompute kernel (1 block): U, O_w = U^dag Z_w U, multilinear coeffs.
// ---------------------------------------------------------------------------
__global__ void precompute_A_kernel(const float* __restrict__ vp) {
    __shared__ float vc[24], vs[24];
    __shared__ float Ur[16][16], Ui[16][16];
    __shared__ float ReO[4][16][16];

    const int tid = threadIdx.x;

    // zero pads (and everything; real entries overwritten below)
    for (int i = tid; i < 9 * 40; i += 324) g_A[i] = 0.0f;

    if (tid < 24) {
        float ss, cc;
        __sincosf(vp[tid] * 0.5f, &ss, &cc);
        vc[tid] = cc;
        vs[tid] = ss;
    }
    __syncthreads();

    if (tid < 16) {
        float sr[16], si[16];
#pragma unroll
        for (int i = 0; i < 16; i++) { sr[i] = 0.0f; si[i] = 0.0f; }
        sr[tid] = 1.0f;

#pragma unroll
        for (int l = 0; l < 3; l++) {
            const float* lc = vc + l * 8;
            const float* ls = vs + l * 8;
            ry_gate<8>(sr, si, lc[0], ls[0]); rz_gate<8>(sr, si, lc[1], ls[1]);
            ry_gate<4>(sr, si, lc[1], ls[1]); rz_gate<4>(sr, si, lc[2], ls[2]);
            ry_gate<2>(sr, si, lc[2], ls[2]); rz_gate<2>(sr, si, lc[3], ls[3]);
            ry_gate<1>(sr, si, lc[3], ls[3]); rz_gate<1>(sr, si, lc[4], ls[4]);
            cx_gate<8, 4>(sr, si);
            cx_gate<4, 2>(sr, si);
            cx_gate<2, 1>(sr, si);
            cx_gate<1, 8>(sr, si);
        }
#pragma unroll
        for (int k = 0; k < 16; k++) { Ur[k][tid] = sr[k]; Ui[k][tid] = si[k]; }
    }
    __syncthreads();

    if (tid < 256) {
        const int i = tid >> 4;
        const int j = tid & 15;
        float acc[4] = {0.0f, 0.0f, 0.0f, 0.0f};
#pragma unroll
        for (int k = 0; k < 16; k++) {
            float t = Ur[k][i] * Ur[k][j] + Ui[k][i] * Ui[k][j];
#pragma unroll
            for (int w = 0; w < 4; w++)
                acc[w] += (k & (8 >> w)) ? -t : t;
        }
#pragma unroll
        for (int w = 0; w < 4; w++) ReO[w][i][j] = acc[w];
    }
    __syncthreads();

    if (tid < 324) {
        const int w = tid / 81;
        const int a = tid % 81;
        const int a0 = a / 27, a1 = (a / 9) % 3, a2 = (a / 3) % 3, a3 = a % 3;
        const int zm = (a0 == 1 ? 8 : 0) | (a1 == 1 ? 4 : 0) | (a2 == 1 ? 2 : 0) | (a3 == 1 ? 1 : 0);
        const int xm = (a0 == 2 ? 8 : 0) | (a1 == 2 ? 4 : 0) | (a2 == 2 ? 2 : 0) | (a3 == 2 ? 1 : 0);
        float acc = 0.0f;
#pragma unroll
        for (int i = 0; i < 16; i++) {
            float v = ReO[w][i][i ^ xm];
            acc += (__popc(i & zm) & 1) ? -v : v;
        }
        const int a12 = a0 * 3 + a1;
        const int a34 = a2 * 3 + a3;
        g_A[a12 * 40 + w * 10 + a34] = acc * 0.0625f;
    }
}

// ---------------------------------------------------------------------------
// Main fused kernel: one block per IMAGE PAIR. Packed f32x2 contraction,
// feats -> smem, then warp-GEMM logits + log_softmax.
// ---------------------------------------------------------------------------
__global__ __launch_bounds__(224) void quanv_fused4_kernel(
    const float* __restrict__ x,     // (B,1,28,28)
    const float* __restrict__ W,     // (10,784)
    const float* __restrict__ bias,  // (10,)
    float* __restrict__ out,         // (B,10)
    int B)
{
    const int b0   = 2 * blockIdx.x;
    const int b1   = b0 + 1;
    const bool has1 = (b1 < B);
    const int tid  = threadIdx.x;
    const int warp = tid >> 5;
    const int lane = tid & 31;

    __shared__ __align__(16) float sA[9 * 40];
    __shared__ __align__(16) float4 feats[2][196];
    __shared__ float slog[20];
    __shared__ float slse[2];

    for (int i = tid; i < 9 * 40; i += 224)
        sA[i] = g_A[i];
    __syncthreads();

    if (tid < 196) {
        const int r14 = tid / 14;
        const int c14 = tid % 14;
        const int off = (2 * r14) * 28 + 2 * c14;

        // ---- image 0 ----
        float g12a[9];
        u64 g34pa[5];
        {
            const float* xa = x + (size_t)b0 * 784;
            const float2 t2 = *reinterpret_cast<const float2*>(xa + off);
            const float2 b2 = *reinterpret_cast<const float2*>(xa + off + 28);
            float c0, s0, c1, s1, c2, s2, c3, s3;
            __sincosf(t2.x, &s0, &c0);
            __sincosf(t2.y, &s1, &c1);
            __sincosf(b2.x, &s2, &c2);
            __sincosf(b2.y, &s3, &c3);
            g12a[0] = 1.0f; g12a[1] = c1;      g12a[2] = s1;
            g12a[3] = c0;   g12a[4] = c0 * c1; g12a[5] = c0 * s1;
            g12a[6] = s0;   g12a[7] = s0 * c1; g12a[8] = s0 * s1;
            // g34 = [1, c3, s3, c2, c2c3, c2s3, s2, s2c3, s2s3] packed in pairs
            g34pa[0] = pk2(1.0f,    c3);
            g34pa[1] = pk2(s3,      c2);
            g34pa[2] = pk2(c2 * c3, c2 * s3);
            g34pa[3] = pk2(s2,      s2 * c3);
            g34pa[4] = pk2(s2 * s3, 0.0f);
        }

        // ---- image 1 ----
        float g12b[9];
        u64 g34pb[5];
        if (has1) {
            const float* xb = x + (size_t)b1 * 784;
            const float2 t2 = *reinterpret_cast<const float2*>(xb + off);
            const float2 b2 = *reinterpret_cast<const float2*>(xb + off + 28);
            float c0, s0, c1, s1, c2, s2, c3, s3;
            __sincosf(t2.x, &s0, &c0);
            __sincosf(t2.y, &s1, &c1);
            __sincosf(b2.x, &s2, &c2);
            __sincosf(b2.y, &s3, &c3);
            g12b[0] = 1.0f; g12b[1] = c1;      g12b[2] = s1;
            g12b[3] = c0;   g12b[4] = c0 * c1; g12b[5] = c0 * s1;
            g12b[6] = s0;   g12b[7] = s0 * c1; g12b[8] = s0 * s1;
            g34pb[0] = pk2(1.0f,    c3);
            g34pb[1] = pk2(s3,      c2);
            g34pb[2] = pk2(c2 * c3, c2 * s3);
            g34pb[3] = pk2(s2,      s2 * c3);
            g34pb[4] = pk2(s2 * s3, 0.0f);
        } else {
#pragma unroll
            for (int i = 0; i < 9; i++) g12b[i] = 0.0f;
#pragma unroll
            for (int i = 0; i < 5; i++) g34pb[i] = 0ull;
        }

        // ---- packed contraction: e2[w] accumulates (even-j, odd-j) partial sums ----
        u64 e2a[4] = {0ull, 0ull, 0ull, 0ull};
        u64 e2b[4] = {0ull, 0ull, 0ull, 0ull};
#pragma unroll
        for (int i = 0; i < 9; i++) {
            const u64 gpa = pk2(g12a[i], g12a[i]);
            const u64 gpb = pk2(g12b[i], g12b[i]);
#pragma unroll
            for (int w = 0; w < 4; w++) {
                const u64* row = reinterpret_cast<const u64*>(&sA[(i * 4 + w) * 10]);
                const u64 a0 = row[0], a1 = row[1], a2 = row[2], a3 = row[3], a4 = row[4];
                u64 ta = mul2(a0, g34pa[0]);
                ta = fma2(a1, g34pa[1], ta);
                ta = fma2(a2, g34pa[2], ta);
                ta = fma2(a3, g34pa[3], ta);
                ta = fma2(a4, g34pa[4], ta);
                u64 tb = mul2(a0, g34pb[0]);
                tb = fma2(a1, g34pb[1], tb);
                tb = fma2(a2, g34pb[2], tb);
                tb = fma2(a3, g34pb[3], tb);
                tb = fma2(a4, g34pb[4], tb);
                e2a[w] = fma2(gpa, ta, e2a[w]);
                e2b[w] = fma2(gpb, tb, e2b[w]);
            }
        }

        float ea[4], eb[4];
#pragma unroll
        for (int w = 0; w < 4; w++) {
            float lo, hi;
            upk2(lo, hi, e2a[w]); ea[w] = lo + hi;
            upk2(lo, hi, e2b[w]); eb[w] = lo + hi;
        }
        feats[0][tid] = make_float4(ea[0], ea[1], ea[2], ea[3]);
        feats[1][tid] = make_float4(eb[0], eb[1], eb[2], eb[3]);
    }
    __syncthreads();

    // ---- warp-GEMM logits: 20 tasks (img,class) over 7 warps ----
#pragma unroll
    for (int r = 0; r < 3; r++) {
        const int task = warp + 7 * r;
        if (task < 20) {
            const int img = task / 10;
            const int c   = task % 10;
            const u64* fv = reinterpret_cast<const u64*>(&feats[img][0]);
            const u64* wv = reinterpret_cast<const u64*>(W + c * 784);
            u64 acc2 = 0ull;
#pragma unroll
            for (int k = 0; k < 7; k++) {
                const int p = 32 * k + lane;
                if (p < 196) {
                    acc2 = fma2(fv[2 * p],     wv[2 * p],     acc2);
                    acc2 = fma2(fv[2 * p + 1], wv[2 * p + 1], acc2);
                }
            }
            float lo, hi;
            upk2(lo, hi, acc2);
            float acc = lo + hi;
#pragma unroll
            for (int off = 16; off > 0; off >>= 1)
                acc += __shfl_xor_sync(0xffffffffu, acc, off);
            if (lane == 0) slog[task] = acc + bias[c];
        }
    }
    __syncthreads();

    if (tid < 2) {
        const float* l = slog + 10 * tid;
        float mx = l[0];
#pragma unroll
        for (int c = 1; c < 10; c++) mx = fmaxf(mx, l[c]);
        float se = 0.0f;
#pragma unroll
        for (int c = 0; c < 10; c++) se += expf(l[c] - mx);
        slse[tid] = mx + logf(se);
    }
    __syncthreads();

    if (tid < 20) {
        const int img = tid / 10;
        if (img == 0 || has1)
            out[(size_t)(b0 + img) * 10 + (tid % 10)] = slog[tid] - slse[img];
    }
}

extern "C" void kernel_launch(void* const* d_in, const int* in_sizes, int n_in,
                              void* d_out, int out_size) {
    const float* x    = (const float*)d_in[0];   // (B,1,28,28)
    const float* vp   = (const float*)d_in[1];   // (3,8)
    const float* W    = (const float*)d_in[2];   // (10,784)
    const float* bias = (const float*)d_in[3];   // (10,)
    float* out = (float*)d_out;

    const int B = in_sizes[0] / 784;
    precompute_A_kernel<<<1, 324>>>(vp);
    quanv_fused4_kernel<<<(B + 1) / 2, 224>>>(x, W, bias, out, B);
}

// round 5
// speedup vs baseline: 1.1957x; 1.1957x over previous
#include <cuda_runtime.h>
#include <math.h>

// ---------------------------------------------------------------------------
// Gate templates (compile-time masks). Wire w <-> bit (3-w) of amp index.
// ---------------------------------------------------------------------------
template<int M>
__device__ __forceinline__ void ry_gate(float sr[16], float si[16], float c, float s) {
#pragma unroll
    for (int i = 0; i < 16; i++) {
        if (!(i & M)) {
            const int j = i | M;
            float a0r = sr[i], a0i = si[i], a1r = sr[j], a1i = si[j];
            sr[i] = c * a0r - s * a1r;
            si[i] = c * a0i - s * a1i;
            sr[j] = s * a0r + c * a1r;
            si[j] = s * a0i + c * a1i;
        }
    }
}

template<int M>
__device__ __forceinline__ void rz_gate(float sr[16], float si[16], float c, float s) {
#pragma unroll
    for (int i = 0; i < 16; i++) {
        float sg = (i & M) ? s : -s;
        float rr = sr[i], ii = si[i];
        sr[i] = c * rr - sg * ii;
        si[i] = c * ii + sg * rr;
    }
}

template<int CM, int TM>
__device__ __forceinline__ void cx_gate(float sr[16], float si[16]) {
#pragma unroll
    for (int i = 0; i < 16; i++) {
        if ((i & CM) && !(i & TM)) {
            const int j = i | TM;
            float t;
            t = sr[i]; sr[i] = sr[j]; sr[j] = t;
            t = si[i]; si[i] = si[j]; si[j] = t;
        }
    }
}

// Coefficient tensor, layout [i(a12)][w*9 + j(a34)]: 9 rows x 36 floats.
__device__ float g_A[9 * 36];

// ---------------------------------------------------------------------------
// Precompute kernel (1 block): U, O_w = U^dag Z_w U, multilinear coeffs.
// ---------------------------------------------------------------------------
__global__ void precompute_A_kernel(const float* __restrict__ vp) {
    __shared__ float vc[24], vs[24];
    __shared__ float Ur[16][16], Ui[16][16];
    __shared__ float ReO[4][16][16];

    const int tid = threadIdx.x;

    if (tid < 24) {
        float ss, cc;
        __sincosf(vp[tid] * 0.5f, &ss, &cc);
        vc[tid] = cc;
        vs[tid] = ss;
    }
    __syncthreads();

    if (tid < 16) {
        float sr[16], si[16];
#pragma unroll
        for (int i = 0; i < 16; i++) { sr[i] = 0.0f; si[i] = 0.0f; }
        sr[tid] = 1.0f;

#pragma unroll
        for (int l = 0; l < 3; l++) {
            const float* lc = vc + l * 8;
            const float* ls = vs + l * 8;
            ry_gate<8>(sr, si, lc[0], ls[0]); rz_gate<8>(sr, si, lc[1], ls[1]);
            ry_gate<4>(sr, si, lc[1], ls[1]); rz_gate<4>(sr, si, lc[2], ls[2]);
            ry_gate<2>(sr, si, lc[2], ls[2]); rz_gate<2>(sr, si, lc[3], ls[3]);
            ry_gate<1>(sr, si, lc[3], ls[3]); rz_gate<1>(sr, si, lc[4], ls[4]);
            cx_gate<8, 4>(sr, si);
            cx_gate<4, 2>(sr, si);
            cx_gate<2, 1>(sr, si);
            cx_gate<1, 8>(sr, si);
        }
#pragma unroll
        for (int k = 0; k < 16; k++) { Ur[k][tid] = sr[k]; Ui[k][tid] = si[k]; }
    }
    __syncthreads();

    if (tid < 256) {
        const int i = tid >> 4;
        const int j = tid & 15;
        float acc[4] = {0.0f, 0.0f, 0.0f, 0.0f};
#pragma unroll
        for (int k = 0; k < 16; k++) {
            float t = Ur[k][i] * Ur[k][j] + Ui[k][i] * Ui[k][j];
#pragma unroll
            for (int w = 0; w < 4; w++)
                acc[w] += (k & (8 >> w)) ? -t : t;
        }
#pragma unroll
        for (int w = 0; w < 4; w++) ReO[w][i][j] = acc[w];
    }
    __syncthreads();

    if (tid < 324) {
        const int w = tid / 81;
        const int a = tid % 81;
        const int a0 = a / 27, a1 = (a / 9) % 3, a2 = (a / 3) % 3, a3 = a % 3;
        const int zm = (a0 == 1 ? 8 : 0) | (a1 == 1 ? 4 : 0) | (a2 == 1 ? 2 : 0) | (a3 == 1 ? 1 : 0);
        const int xm = (a0 == 2 ? 8 : 0) | (a1 == 2 ? 4 : 0) | (a2 == 2 ? 2 : 0) | (a3 == 2 ? 1 : 0);
        float acc = 0.0f;
#pragma unroll
        for (int i = 0; i < 16; i++) {
            float v = ReO[w][i][i ^ xm];
            acc += (__popc(i & zm) & 1) ? -v : v;
        }
        const int a12 = a0 * 3 + a1;
        const int a34 = a2 * 3 + a3;
        g_A[a12 * 36 + w * 9 + a34] = acc * 0.0625f;
    }
}

// ---------------------------------------------------------------------------
// Main fused kernel: one block per IMAGE PAIR. R3 contraction (float4 LDS,
// scalar FMA) -> feats to smem -> warp-GEMM logits -> log_softmax.
// ---------------------------------------------------------------------------
__global__ __launch_bounds__(224, 5) void quanv_fused5_kernel(
    const float* __restrict__ x,     // (B,1,28,28)
    const float* __restrict__ W,     // (10,784)
    const float* __restrict__ bias,  // (10,)
    float* __restrict__ out,         // (B,10)
    int B)
{
    const int b0   = 2 * blockIdx.x;
    const int b1   = b0 + 1;
    const bool has1 = (b1 < B);
    const int tid  = threadIdx.x;
    const int warp = tid >> 5;
    const int lane = tid & 31;

    __shared__ __align__(16) float sA[9 * 36];
    __shared__ __align__(16) float4 feats[2][196];
    __shared__ float slog[20];
    __shared__ float slse[2];

    for (int i = tid; i < 9 * 36; i += 224)
        sA[i] = g_A[i];
    __syncthreads();

    if (tid < 196) {
        const int r14 = tid / 14;
        const int c14 = tid % 14;
        const int off = (2 * r14) * 28 + 2 * c14;

        // ---- image 0 angles ----
        float g12a[9], g34a[9];
        {
            const float* xa = x + (size_t)b0 * 784;
            const float2 t2 = *reinterpret_cast<const float2*>(xa + off);
            const float2 b2 = *reinterpret_cast<const float2*>(xa + off + 28);
            float c0, s0, c1, s1, c2, s2, c3, s3;
            __sincosf(t2.x, &s0, &c0);
            __sincosf(t2.y, &s1, &c1);
            __sincosf(b2.x, &s2, &c2);
            __sincosf(b2.y, &s3, &c3);
            g12a[0] = 1.0f; g12a[1] = c1;      g12a[2] = s1;
            g12a[3] = c0;   g12a[4] = c0 * c1; g12a[5] = c0 * s1;
            g12a[6] = s0;   g12a[7] = s0 * c1; g12a[8] = s0 * s1;
            g34a[0] = 1.0f; g34a[1] = c3;      g34a[2] = s3;
            g34a[3] = c2;   g34a[4] = c2 * c3; g34a[5] = c2 * s3;
            g34a[6] = s2;   g34a[7] = s2 * c3; g34a[8] = s2 * s3;
        }

        // ---- image 1 angles ----
        float g12b[9], g34b[9];
        if (has1) {
            const float* xb = x + (size_t)b1 * 784;
            const float2 t2 = *reinterpret_cast<const float2*>(xb + off);
            const float2 b2 = *reinterpret_cast<const float2*>(xb + off + 28);
            float c0, s0, c1, s1, c2, s2, c3, s3;
            __sincosf(t2.x, &s0, &c0);
            __sincosf(t2.y, &s1, &c1);
            __sincosf(b2.x, &s2, &c2);
            __sincosf(b2.y, &s3, &c3);
            g12b[0] = 1.0f; g12b[1] = c1;      g12b[2] = s1;
            g12b[3] = c0;   g12b[4] = c0 * c1; g12b[5] = c0 * s1;
            g12b[6] = s0;   g12b[7] = s0 * c1; g12b[8] = s0 * s1;
            g34b[0] = 1.0f; g34b[1] = c3;      g34b[2] = s3;
            g34b[3] = c2;   g34b[4] = c2 * c3; g34b[5] = c2 * s3;
            g34b[6] = s2;   g34b[7] = s2 * c3; g34b[8] = s2 * s3;
        } else {
#pragma unroll
            for (int i = 0; i < 9; i++) { g12b[i] = 0.0f; g34b[i] = 0.0f; }
        }

        // ---- contraction: e_w = g12^T A_w g34, A row shared by both images ----
        float e0[4] = {0.f, 0.f, 0.f, 0.f};
        float e1[4] = {0.f, 0.f, 0.f, 0.f};
#pragma unroll
        for (int i = 0; i < 9; i++) {
            float av[36];
#pragma unroll
            for (int q = 0; q < 9; q++)
                *reinterpret_cast<float4*>(av + 4 * q) =
                    *reinterpret_cast<const float4*>(&sA[i * 36 + 4 * q]);
#pragma unroll
            for (int w = 0; w < 4; w++) {
                const float* aw = av + w * 9;
                float t0 = aw[0] * g34a[0];
                float t1 = aw[0] * g34b[0];
#pragma unroll
                for (int j = 1; j < 9; j++) {
                    t0 = fmaf(aw[j], g34a[j], t0);
                    t1 = fmaf(aw[j], g34b[j], t1);
                }
                e0[w] = fmaf(g12a[i], t0, e0[w]);
                e1[w] = fmaf(g12b[i], t1, e1[w]);
            }
        }

        feats[0][tid] = make_float4(e0[0], e0[1], e0[2], e0[3]);
        feats[1][tid] = make_float4(e1[0], e1[1], e1[2], e1[3]);
    }
    __syncthreads();

    // ---- warp-GEMM logits: 20 tasks (img,class) over 7 warps ----
#pragma unroll
    for (int r = 0; r < 3; r++) {
        const int task = warp + 7 * r;
        if (task < 20) {
            const int img = task / 10;
            const int c   = task % 10;
            const float* wrow = W + c * 784;
            float acc = 0.0f;
#pragma unroll
            for (int k = 0; k < 7; k++) {
                const int p = 32 * k + lane;
                if (p < 196) {
                    const float4 fv = feats[img][p];
                    const float4 wv = *reinterpret_cast<const float4*>(wrow + 4 * p);
                    acc = fmaf(fv.x, wv.x, acc);
                    acc = fmaf(fv.y, wv.y, acc);
                    acc = fmaf(fv.z, wv.z, acc);
                    acc = fmaf(fv.w, wv.w, acc);
                }
            }
#pragma unroll
            for (int off = 16; off > 0; off >>= 1)
                acc += __shfl_xor_sync(0xffffffffu, acc, off);
            if (lane == 0) slog[task] = acc + bias[c];
        }
    }
    __syncthreads();

    if (tid < 2) {
        const float* l = slog + 10 * tid;
        float mx = l[0];
#pragma unroll
        for (int c = 1; c < 10; c++) mx = fmaxf(mx, l[c]);
        float se = 0.0f;
#pragma unroll
        for (int c = 0; c < 10; c++) se += expf(l[c] - mx);
        slse[tid] = mx + logf(se);
    }
    __syncthreads();

    if (tid < 20) {
        const int img = tid / 10;
        if (img == 0 || has1)
            out[(size_t)(b0 + img) * 10 + (tid % 10)] = slog[tid] - slse[img];
    }
}

extern "C" void kernel_launch(void* const* d_in, const int* in_sizes, int n_in,
                              void* d_out, int out_size) {
    const float* x    = (const float*)d_in[0];   // (B,1,28,28)
    const float* vp   = (const float*)d_in[1];   // (3,8)
    const float* W    = (const float*)d_in[2];   // (10,784)
    const float* bias = (const float*)d_in[3];   // (10,)
    float* out = (float*)d_out;

    const int B = in_sizes[0] / 784;
    precompute_A_kernel<<<1, 324>>>(vp);
    quanv_fused5_kernel<<<(B + 1) / 2, 224>>>(x, W, bias, out, B);
}